// round 7
// baseline (speedup 1.0000x reference)
#include <cuda_runtime.h>
#include <cuda_bf16.h>
#include <math.h>
#include <cstdint>

#define BATCH 4
#define SEQ   2048
#define DM    1024
#define NH    16
#define HD    64
#define QKVN  (3*DM)
#define MROWS (BATCH*SEQ)   // 8192

// ---------------------------------------------------------------------------
// Persistent bf16 hi/lo arrays (no dynamic allocation allowed)
// ---------------------------------------------------------------------------
__device__ __nv_bfloat16 g_xh[(size_t)MROWS * DM];
__device__ __nv_bfloat16 g_xl[(size_t)MROWS * DM];
__device__ __nv_bfloat16 g_wqh[(size_t)DM * QKVN];
__device__ __nv_bfloat16 g_wql[(size_t)DM * QKVN];
__device__ __nv_bfloat16 g_woh[(size_t)DM * DM];
__device__ __nv_bfloat16 g_wol[(size_t)DM * DM];
__device__ __nv_bfloat16 g_qkvh[(size_t)MROWS * QKVN];
__device__ __nv_bfloat16 g_qkvl[(size_t)MROWS * QKVN];
__device__ __nv_bfloat16 g_atth[(size_t)MROWS * DM];
__device__ __nv_bfloat16 g_attl[(size_t)MROWS * DM];

// ===========================================================================
// Helpers
// ===========================================================================
__device__ __forceinline__ void ldsm_x4(uint32_t* r, uint32_t addr) {
    asm volatile("ldmatrix.sync.aligned.m8n8.x4.shared.b16 {%0,%1,%2,%3}, [%4];"
        : "=r"(r[0]), "=r"(r[1]), "=r"(r[2]), "=r"(r[3]) : "r"(addr));
}
__device__ __forceinline__ void ldsm_x4_t(uint32_t* r, uint32_t addr) {
    asm volatile("ldmatrix.sync.aligned.m8n8.x4.trans.shared.b16 {%0,%1,%2,%3}, [%4];"
        : "=r"(r[0]), "=r"(r[1]), "=r"(r[2]), "=r"(r[3]) : "r"(addr));
}
__device__ __forceinline__ void mma16816(float* d, const uint32_t* a, const uint32_t* b) {
    asm volatile(
        "mma.sync.aligned.m16n8k16.row.col.f32.bf16.bf16.f32 "
        "{%0,%1,%2,%3}, {%4,%5,%6,%7}, {%8,%9}, {%0,%1,%2,%3};"
        : "+f"(d[0]), "+f"(d[1]), "+f"(d[2]), "+f"(d[3])
        : "r"(a[0]), "r"(a[1]), "r"(a[2]), "r"(a[3]), "r"(b[0]), "r"(b[1]));
}
__device__ __forceinline__ uint32_t smem_to_u32(const void* smem_ptr) {
    uint32_t addr;
    asm("{ .reg .u64 tmp; cvta.to.shared.u64 tmp, %1; cvt.u32.u64 %0, tmp; }"
        : "=r"(addr) : "l"(smem_ptr));
    return addr;
}
__device__ __forceinline__ float ex2f(float x) {
    float y;
    asm("ex2.approx.f32 %0, %1;" : "=f"(y) : "f"(x));
    return y;
}
__device__ __forceinline__ uint32_t pack_bf16_pair(float x0, float x1) {
    __nv_bfloat162 t = __floats2bfloat162_rn(x0, x1);
    return *(uint32_t*)&t;
}
__device__ __forceinline__ void split_f32(float x, float& h, float& l) {
    __nv_bfloat16 hb = __float2bfloat16_rn(x);
    h = __bfloat162float(hb);
    l = x - h;
}

#define CP_ASYNC16(saddr, gptr) \
    asm volatile("cp.async.cg.shared.global [%0], [%1], 16;" \
                 :: "r"(saddr), "l"(gptr))
#define CP_COMMIT()  asm volatile("cp.async.commit_group;")
#define CP_WAIT0()   asm volatile("cp.async.wait_group 0;")
#define CP_WAIT1()   asm volatile("cp.async.wait_group 1;")

// ===========================================================================
// Split kernel: fp32 -> bf16 hi/lo
// ===========================================================================
__global__ void split_kernel(const float* __restrict__ s,
                             __nv_bfloat16* __restrict__ h,
                             __nv_bfloat16* __restrict__ l, int n4)
{
    int i = blockIdx.x * blockDim.x + threadIdx.x;
    if (i >= n4) return;
    float4 v = ((const float4*)s)[i];
    float h0,l0,h1,l1,h2,l2,h3,l3;
    split_f32(v.x, h0, l0); split_f32(v.y, h1, l1);
    split_f32(v.z, h2, l2); split_f32(v.w, h3, l3);
    ((uint2*)h)[i] = make_uint2(pack_bf16_pair(h0, h1), pack_bf16_pair(h2, h3));
    ((uint2*)l)[i] = make_uint2(pack_bf16_pair(l0, l1), pack_bf16_pair(l2, l3));
}

// ===========================================================================
// cp.async bf16x3 GEMM: C = A @ B; A,B pre-split hi/lo bf16 in global.
// CTA tile 128x256, BK=32, 256 threads (8 warps, 64x64 warp tiles 2x4).
// 3-stage cp.async ring, one barrier per k-tile.
// Output: fp32 (Cf) OR hi/lo bf16 (Ch/Cl) with scale qscale for cols<qcols.
// ===========================================================================
// per-stage smem layout (bytes): Ah 128x80, Al, Bh 32x528, Bl
#define GOAH 0
#define GOAL 10240
#define GOBH 20480
#define GOBL 37376
#define GSTAGE_B 54272
#define GEMM_SMEM_BYTES (3 * GSTAGE_B)   // 162816

__global__ __launch_bounds__(256, 1)
void gemm_async(const __nv_bfloat16* __restrict__ Ah, const __nv_bfloat16* __restrict__ Al,
                const __nv_bfloat16* __restrict__ Bh, const __nv_bfloat16* __restrict__ Bl,
                float* __restrict__ Cf,
                __nv_bfloat16* __restrict__ Ch, __nv_bfloat16* __restrict__ Cl,
                int M, int N, int K, float qscale, int qcols)
{
    extern __shared__ char smem[];
    const uint32_t su = smem_to_u32(smem);

    const int tid = threadIdx.x;
    const int wid = tid >> 5;
    const int lid = tid & 31;
    const int brow = blockIdx.y * 128;
    const int bcol = blockIdx.x * 256;

    const int wr = wid >> 2;     // 0..1 -> m offset wr*64
    const int wc = wid & 3;      // 0..3 -> n offset wc*64

    const int nkt = K >> 5;

    // copy-thread assignments
    const int ar  = tid >> 1;            // A row 0..127
    const int ac2 = (tid & 1) * 2;       // A chunk base 0 or 2 (chunks of 16B = 8 elems)
    const int br  = tid >> 3;            // B row 0..31
    const int bc4 = (tid & 7) * 4;       // B chunk base (chunks of 8 elems)

    auto issue_tile = [&](int kt) {
        const int st = kt % 3;
        const uint32_t sb = su + st * GSTAGE_B;
        const int k0 = kt << 5;
        const __nv_bfloat16* gah = Ah + (size_t)(brow + ar) * K + k0 + ac2 * 8;
        const __nv_bfloat16* gal = Al + (size_t)(brow + ar) * K + k0 + ac2 * 8;
        uint32_t sa = sb + GOAH + ar * 80 + ac2 * 16;
        uint32_t sal = sb + GOAL + ar * 80 + ac2 * 16;
        CP_ASYNC16(sa,       gah);
        CP_ASYNC16(sa + 16,  gah + 8);
        CP_ASYNC16(sal,      gal);
        CP_ASYNC16(sal + 16, gal + 8);
        const __nv_bfloat16* gbh = Bh + (size_t)(k0 + br) * N + bcol + bc4 * 8;
        const __nv_bfloat16* gbl = Bl + (size_t)(k0 + br) * N + bcol + bc4 * 8;
        uint32_t sbh = sb + GOBH + br * 528 + bc4 * 16;
        uint32_t sbl = sb + GOBL + br * 528 + bc4 * 16;
#pragma unroll
        for (int c = 0; c < 4; c++) {
            CP_ASYNC16(sbh + c * 16, gbh + c * 8);
            CP_ASYNC16(sbl + c * 16, gbl + c * 8);
        }
    };

    float acc[4][8][4];
#pragma unroll
    for (int i = 0; i < 4; i++)
#pragma unroll
        for (int j = 0; j < 8; j++)
#pragma unroll
            for (int q = 0; q < 4; q++) acc[i][j][q] = 0.f;

    issue_tile(0); CP_COMMIT();
    issue_tile(1); CP_COMMIT();

    for (int kt = 0; kt < nkt; kt++) {
        if (kt + 1 < nkt) { CP_WAIT1(); } else { CP_WAIT0(); }
        __syncthreads();
        if (kt + 2 < nkt) { issue_tile(kt + 2); CP_COMMIT(); }

        const uint32_t sb = su + (kt % 3) * GSTAGE_B;
#pragma unroll
        for (int ks = 0; ks < 2; ks++) {
            uint32_t ah[4][4], al[4][4];
#pragma unroll
            for (int mi = 0; mi < 4; mi++) {
                uint32_t row = wr * 64 + mi * 16 + (lid & 15);
                uint32_t col = ks * 16 + (lid >> 4) * 8;
                uint32_t off = row * 80 + col * 2;
                ldsm_x4(ah[mi], sb + GOAH + off);
                ldsm_x4(al[mi], sb + GOAL + off);
            }
#pragma unroll
            for (int nb = 0; nb < 4; nb++) {
                uint32_t bh[4], bl[4];
                uint32_t row = ks * 16 + (lid & 15);
                uint32_t col = wc * 64 + nb * 16 + (lid >> 4) * 8;
                uint32_t off = row * 528 + col * 2;
                ldsm_x4_t(bh, sb + GOBH + off);
                ldsm_x4_t(bl, sb + GOBL + off);
#pragma unroll
                for (int pass = 0; pass < 3; pass++) {
#pragma unroll
                    for (int mi = 0; mi < 4; mi++) {
                        const uint32_t* af = (pass == 2) ? al[mi] : ah[mi];
                        const uint32_t* bf = (pass == 1) ? bl : bh;
                        mma16816(acc[mi][nb * 2],     af, &bf[0]);
                        mma16816(acc[mi][nb * 2 + 1], af, &bf[2]);
                    }
                }
            }
        }
    }

    // ---- epilogue ----
    const int qrow = lid >> 2;
    const int qcol = (lid & 3) * 2;
#pragma unroll
    for (int mi = 0; mi < 4; mi++) {
        int r0 = brow + wr * 64 + mi * 16 + qrow;
#pragma unroll
        for (int nb8 = 0; nb8 < 8; nb8++) {
            int c0 = bcol + wc * 64 + nb8 * 8 + qcol;
            float* d = acc[mi][nb8];
            if (Cf) {
                *(float2*)(Cf + (size_t)r0 * N + c0)       = make_float2(d[0], d[1]);
                *(float2*)(Cf + (size_t)(r0 + 8) * N + c0) = make_float2(d[2], d[3]);
            } else {
                const float sc = (c0 < qcols) ? qscale : 1.f;
                float h0,l0,h1,l1;
                split_f32(d[0] * sc, h0, l0); split_f32(d[1] * sc, h1, l1);
                *(uint32_t*)(Ch + (size_t)r0 * N + c0) = pack_bf16_pair(h0, h1);
                *(uint32_t*)(Cl + (size_t)r0 * N + c0) = pack_bf16_pair(l0, l1);
                split_f32(d[2] * sc, h0, l0); split_f32(d[3] * sc, h1, l1);
                *(uint32_t*)(Ch + (size_t)(r0 + 8) * N + c0) = pack_bf16_pair(h0, h1);
                *(uint32_t*)(Cl + (size_t)(r0 + 8) * N + c0) = pack_bf16_pair(l0, l1);
            }
        }
    }
}

// ===========================================================================
// HMMA flash attention, bf16x3, cp.async-fed K/V (pre-split in g_qkvh/l).
// Grid: (SEQ/256, NH, BATCH). 256 threads = 8 warps; warp w owns q rows
// [w*32, w*32+32). Q persists in smem; K/V 3-stage ring, 1 barrier/block.
// ===========================================================================
#define SK 72
// dynamic smem layout (bytes):
#define AQHI 0
#define AQLO (256 * SK * 2)            // 36864
#define AKV  (2 * 256 * SK * 2)        // 73728
#define KVST (4 * 64 * SK * 2)         // 36864 per stage
#define OKHI 0
#define OKLO (64 * SK * 2)             // 9216
#define OVHI (2 * 64 * SK * 2)
#define OVLO (3 * 64 * SK * 2)
#define ATTN_SMEM_BYTES (AKV + 3 * KVST)   // 184320

__global__ __launch_bounds__(256, 1)
void attn_hmma()
{
    extern __shared__ char dsm[];
    const uint32_t su = smem_to_u32(dsm);

    const int tid = threadIdx.x;
    const int wid = tid >> 5;
    const int lid = tid & 31;
    const int b  = blockIdx.z;
    const int h  = blockIdx.y;
    const int q0 = blockIdx.x * 256;

    const uint32_t uQhi = su + AQHI, uQlo = su + AQLO;

    // KV copy assignment: arr = tid>>6 (0:Kh 1:Kl 2:Vh 3:Vl), row = tid&63
    const int cv_arr = tid >> 6;
    const int cv_r   = tid & 63;
    const __nv_bfloat16* cv_base =
        (cv_arr & 1) ? g_qkvl : g_qkvh;
    const int cv_col = DM + (cv_arr >> 1) * DM + h * HD;   // K or V region

    auto issue_kv = [&](int kb) {
        const uint32_t sb = su + AKV + (uint32_t)(kb % 3) * KVST + cv_arr * (64 * SK * 2)
                            + cv_r * (SK * 2);
        const __nv_bfloat16* gp = cv_base +
            (size_t)(b * SEQ + kb * 64 + cv_r) * QKVN + cv_col;
#pragma unroll
        for (int c = 0; c < 8; c++)
            CP_ASYNC16(sb + c * 16, gp + c * 8);
    };

    // ---- issue Q (row tid for hi and lo) + KV block 0 as group 0
    {
        const __nv_bfloat16* gqh = g_qkvh + (size_t)(b * SEQ + q0 + tid) * QKVN + h * HD;
        const __nv_bfloat16* gql = g_qkvl + (size_t)(b * SEQ + q0 + tid) * QKVN + h * HD;
        uint32_t sqh = uQhi + tid * (SK * 2);
        uint32_t sql = uQlo + tid * (SK * 2);
#pragma unroll
        for (int c = 0; c < 8; c++) {
            CP_ASYNC16(sqh + c * 16, gqh + c * 8);
            CP_ASYNC16(sql + c * 16, gql + c * 8);
        }
    }
    issue_kv(0); CP_COMMIT();
    issue_kv(1); CP_COMMIT();

    float o[2][8][4];
#pragma unroll
    for (int mi = 0; mi < 2; mi++)
#pragma unroll
        for (int j = 0; j < 8; j++)
#pragma unroll
            for (int q = 0; q < 4; q++) o[mi][j][q] = 0.f;
    float mst[2][2], lst[2][2];
#pragma unroll
    for (int mi = 0; mi < 2; mi++) {
        mst[mi][0] = -1e30f; mst[mi][1] = -1e30f;
        lst[mi][0] = 0.f;    lst[mi][1] = 0.f;
    }

    for (int kb = 0; kb < SEQ / 64; kb++) {
        if (kb + 1 < SEQ / 64) { CP_WAIT1(); } else { CP_WAIT0(); }
        __syncthreads();
        if (kb + 2 < SEQ / 64) { issue_kv(kb + 2); CP_COMMIT(); }

        const uint32_t stB = su + AKV + (uint32_t)(kb % 3) * KVST;
        const uint32_t uKhi = stB + OKHI, uKlo = stB + OKLO;
        const uint32_t uVhi = stB + OVHI, uVlo = stB + OVLO;

        // ---- S = Q K^T  (32 x 64 per warp), bf16x3; K frags shared across mi
        float s[2][8][4];
#pragma unroll
        for (int mi = 0; mi < 2; mi++)
#pragma unroll
            for (int j = 0; j < 8; j++)
#pragma unroll
                for (int q = 0; q < 4; q++) s[mi][j][q] = 0.f;

#pragma unroll
        for (int t = 0; t < 4; t++) {
            uint32_t qh[2][4], ql[2][4];
#pragma unroll
            for (int mi = 0; mi < 2; mi++) {
                uint32_t row = wid * 32 + mi * 16 + (lid & 15);
                uint32_t off = (row * SK + t * 16 + (lid >> 4) * 8) * 2;
                ldsm_x4(qh[mi], uQhi + off);
                ldsm_x4(ql[mi], uQlo + off);
            }
#pragma unroll
            for (int j2 = 0; j2 < 4; j2++) {
                uint32_t kh[4], kl[4];
                uint32_t off = ((j2 * 16 + (lid & 7) + ((lid >> 4) & 1) * 8) * SK
                                + t * 16 + ((lid >> 3) & 1) * 8) * 2;
                ldsm_x4(kh, uKhi + off);
                ldsm_x4(kl, uKlo + off);
#pragma unroll
                for (int mi = 0; mi < 2; mi++) {
                    float* d0 = s[mi][j2 * 2];
                    float* d1 = s[mi][j2 * 2 + 1];
                    mma16816(d0, qh[mi], &kh[0]); mma16816(d1, qh[mi], &kh[2]);
                    mma16816(d0, qh[mi], &kl[0]); mma16816(d1, qh[mi], &kl[2]);
                    mma16816(d0, ql[mi], &kh[0]); mma16816(d1, ql[mi], &kh[2]);
                }
            }
        }

        // ---- online softmax (log2 domain) + pack P
        uint32_t phi[2][4][4], plo[2][4][4];
#pragma unroll
        for (int mi = 0; mi < 2; mi++) {
            float mx0 = s[mi][0][0], mx1 = s[mi][0][2];
#pragma unroll
            for (int j = 0; j < 8; j++) {
                mx0 = fmaxf(mx0, fmaxf(s[mi][j][0], s[mi][j][1]));
                mx1 = fmaxf(mx1, fmaxf(s[mi][j][2], s[mi][j][3]));
            }
            mx0 = fmaxf(mx0, __shfl_xor_sync(0xffffffff, mx0, 1));
            mx0 = fmaxf(mx0, __shfl_xor_sync(0xffffffff, mx0, 2));
            mx1 = fmaxf(mx1, __shfl_xor_sync(0xffffffff, mx1, 1));
            mx1 = fmaxf(mx1, __shfl_xor_sync(0xffffffff, mx1, 2));

            const float mn0 = fmaxf(mst[mi][0], mx0);
            const float mn1 = fmaxf(mst[mi][1], mx1);
            const float c0 = ex2f(mst[mi][0] - mn0);
            const float c1 = ex2f(mst[mi][1] - mn1);
            mst[mi][0] = mn0; mst[mi][1] = mn1;

            float rl0 = 0.f, rl1 = 0.f;
#pragma unroll
            for (int j = 0; j < 8; j++) {
                s[mi][j][0] = ex2f(s[mi][j][0] - mn0); rl0 += s[mi][j][0];
                s[mi][j][1] = ex2f(s[mi][j][1] - mn0); rl0 += s[mi][j][1];
                s[mi][j][2] = ex2f(s[mi][j][2] - mn1); rl1 += s[mi][j][2];
                s[mi][j][3] = ex2f(s[mi][j][3] - mn1); rl1 += s[mi][j][3];
            }
            rl0 += __shfl_xor_sync(0xffffffff, rl0, 1);
            rl0 += __shfl_xor_sync(0xffffffff, rl0, 2);
            rl1 += __shfl_xor_sync(0xffffffff, rl1, 1);
            rl1 += __shfl_xor_sync(0xffffffff, rl1, 2);
            lst[mi][0] = lst[mi][0] * c0 + rl0;
            lst[mi][1] = lst[mi][1] * c1 + rl1;

#pragma unroll
            for (int j = 0; j < 8; j++) {
                o[mi][j][0] *= c0; o[mi][j][1] *= c0;
                o[mi][j][2] *= c1; o[mi][j][3] *= c1;
            }

#pragma unroll
            for (int t = 0; t < 4; t++) {
                const int j = 2 * t;
                float h0,lo0,h1,lo1;
                split_f32(s[mi][j][0], h0, lo0);   split_f32(s[mi][j][1], h1, lo1);
                phi[mi][t][0] = pack_bf16_pair(h0, h1);  plo[mi][t][0] = pack_bf16_pair(lo0, lo1);
                split_f32(s[mi][j][2], h0, lo0);   split_f32(s[mi][j][3], h1, lo1);
                phi[mi][t][1] = pack_bf16_pair(h0, h1);  plo[mi][t][1] = pack_bf16_pair(lo0, lo1);
                split_f32(s[mi][j+1][0], h0, lo0); split_f32(s[mi][j+1][1], h1, lo1);
                phi[mi][t][2] = pack_bf16_pair(h0, h1);  plo[mi][t][2] = pack_bf16_pair(lo0, lo1);
                split_f32(s[mi][j+1][2], h0, lo0); split_f32(s[mi][j+1][3], h1, lo1);
                phi[mi][t][3] = pack_bf16_pair(h0, h1);  plo[mi][t][3] = pack_bf16_pair(lo0, lo1);
            }
        }

        // ---- O += P V  (bf16x3); V frags shared across mi
#pragma unroll
        for (int t = 0; t < 4; t++) {
#pragma unroll
            for (int j2 = 0; j2 < 4; j2++) {
                uint32_t vh[4], vl[4];
                uint32_t off = ((t * 16 + (lid & 15)) * SK
                                + j2 * 16 + (lid >> 4) * 8) * 2;
                ldsm_x4_t(vh, uVhi + off);
                ldsm_x4_t(vl, uVlo + off);
#pragma unroll
                for (int mi = 0; mi < 2; mi++) {
                    float* d0 = o[mi][j2 * 2];
                    float* d1 = o[mi][j2 * 2 + 1];
                    mma16816(d0, phi[mi][t], &vh[0]); mma16816(d1, phi[mi][t], &vh[2]);
                    mma16816(d0, phi[mi][t], &vl[0]); mma16816(d1, phi[mi][t], &vl[2]);
                    mma16816(d0, plo[mi][t], &vh[0]); mma16816(d1, plo[mi][t], &vh[2]);
                }
            }
        }
    }

    // ---- epilogue: write hi/lo bf16 attention output
#pragma unroll
    for (int mi = 0; mi < 2; mi++) {
        const float inv0 = 1.f / lst[mi][0];
        const float inv1 = 1.f / lst[mi][1];
        const int gr0 = q0 + wid * 32 + mi * 16 + (lid >> 2);
        const int col = h * HD + (lid & 3) * 2;
#pragma unroll
        for (int j = 0; j < 8; j++) {
            size_t i0 = (size_t)(b * SEQ + gr0) * DM + col + j * 8;
            size_t i1 = (size_t)(b * SEQ + gr0 + 8) * DM + col + j * 8;
            float h0,l0,h1,l1;
            split_f32(o[mi][j][0] * inv0, h0, l0);
            split_f32(o[mi][j][1] * inv0, h1, l1);
            *(uint32_t*)(g_atth + i0) = pack_bf16_pair(h0, h1);
            *(uint32_t*)(g_attl + i0) = pack_bf16_pair(l0, l1);
            split_f32(o[mi][j][2] * inv1, h0, l0);
            split_f32(o[mi][j][3] * inv1, h1, l1);
            *(uint32_t*)(g_atth + i1) = pack_bf16_pair(h0, h1);
            *(uint32_t*)(g_attl + i1) = pack_bf16_pair(l0, l1);
        }
    }
}

// ---------------------------------------------------------------------------
extern "C" void kernel_launch(void* const* d_in, const int* in_sizes, int n_in,
                              void* d_out, int out_size)
{
    const float* x     = (const float*)d_in[0];   // [4,2048,1024]
    const float* w_qkv = (const float*)d_in[1];   // [1024,3072]
    const float* w_out = (const float*)d_in[2];   // [1024,1024]
    float* out = (float*)d_out;                   // [4,2048,1024]

    __nv_bfloat16 *xh, *xl, *wqh, *wql, *woh, *wol, *qkvh, *qkvl, *atth, *attl;
    cudaGetSymbolAddress((void**)&xh,  g_xh);   cudaGetSymbolAddress((void**)&xl,  g_xl);
    cudaGetSymbolAddress((void**)&wqh, g_wqh);  cudaGetSymbolAddress((void**)&wql, g_wql);
    cudaGetSymbolAddress((void**)&woh, g_woh);  cudaGetSymbolAddress((void**)&wol, g_wol);
    cudaGetSymbolAddress((void**)&qkvh, g_qkvh); cudaGetSymbolAddress((void**)&qkvl, g_qkvl);
    cudaGetSymbolAddress((void**)&atth, g_atth); cudaGetSymbolAddress((void**)&attl, g_attl);

    cudaFuncSetAttribute(gemm_async,
                         cudaFuncAttributeMaxDynamicSharedMemorySize,
                         GEMM_SMEM_BYTES);
    cudaFuncSetAttribute(attn_hmma,
                         cudaFuncAttributeMaxDynamicSharedMemorySize,
                         ATTN_SMEM_BYTES);

    const float QSCALE = 0.125f * 1.4426950408889634f;   // (1/sqrt(64))*log2(e)

    // 0) split inputs to bf16 hi/lo
    {
        int n4x = MROWS * DM / 4;
        split_kernel<<<(n4x + 255) / 256, 256>>>(x, xh, xl, n4x);
        int n4q = DM * QKVN / 4;
        split_kernel<<<(n4q + 255) / 256, 256>>>(w_qkv, wqh, wql, n4q);
        int n4o = DM * DM / 4;
        split_kernel<<<(n4o + 255) / 256, 256>>>(w_out, woh, wol, n4o);
    }

    // 1) QKV projection -> hi/lo bf16 (Q columns pre-scaled by QSCALE)
    {
        dim3 grid(QKVN / 256, MROWS / 128);
        gemm_async<<<grid, 256, GEMM_SMEM_BYTES>>>(
            xh, xl, wqh, wql, nullptr, qkvh, qkvl,
            MROWS, QKVN, DM, QSCALE, DM);
    }

    // 2) Attention (HMMA flash, cp.async K/V)
    {
        dim3 grid(SEQ / 256, NH, BATCH);
        attn_hmma<<<grid, 256, ATTN_SMEM_BYTES>>>();
    }

    // 3) Output projection -> fp32 d_out
    {
        dim3 grid(DM / 256, MROWS / 128);
        gemm_async<<<grid, 256, GEMM_SMEM_BYTES>>>(
            atth, attl, woh, wol, out, nullptr, nullptr,
            MROWS, DM, DM, 1.f, 0);
    }
}

// round 8
// speedup vs baseline: 1.0912x; 1.0912x over previous
#include <cuda_runtime.h>
#include <cuda_bf16.h>
#include <math.h>
#include <cstdint>

#define BATCH 4
#define SEQ   2048
#define DM    1024
#define NH    16
#define HD    64
#define QKVN  (3*DM)
#define MROWS (BATCH*SEQ)   // 8192

// ---------------------------------------------------------------------------
// Persistent bf16 hi/lo arrays (no dynamic allocation allowed)
// ---------------------------------------------------------------------------
__device__ __nv_bfloat16 g_xh[(size_t)MROWS * DM];
__device__ __nv_bfloat16 g_xl[(size_t)MROWS * DM];
__device__ __nv_bfloat16 g_wqh[(size_t)DM * QKVN];
__device__ __nv_bfloat16 g_wql[(size_t)DM * QKVN];
__device__ __nv_bfloat16 g_woh[(size_t)DM * DM];
__device__ __nv_bfloat16 g_wol[(size_t)DM * DM];
__device__ __nv_bfloat16 g_qkvh[(size_t)MROWS * QKVN];
__device__ __nv_bfloat16 g_qkvl[(size_t)MROWS * QKVN];
__device__ __nv_bfloat16 g_atth[(size_t)MROWS * DM];
__device__ __nv_bfloat16 g_attl[(size_t)MROWS * DM];

// ===========================================================================
// Helpers
// ===========================================================================
__device__ __forceinline__ void ldsm_x4(uint32_t* r, uint32_t addr) {
    asm volatile("ldmatrix.sync.aligned.m8n8.x4.shared.b16 {%0,%1,%2,%3}, [%4];"
        : "=r"(r[0]), "=r"(r[1]), "=r"(r[2]), "=r"(r[3]) : "r"(addr));
}
__device__ __forceinline__ void ldsm_x4_t(uint32_t* r, uint32_t addr) {
    asm volatile("ldmatrix.sync.aligned.m8n8.x4.trans.shared.b16 {%0,%1,%2,%3}, [%4];"
        : "=r"(r[0]), "=r"(r[1]), "=r"(r[2]), "=r"(r[3]) : "r"(addr));
}
__device__ __forceinline__ void mma16816(float* d, const uint32_t* a, const uint32_t* b) {
    asm volatile(
        "mma.sync.aligned.m16n8k16.row.col.f32.bf16.bf16.f32 "
        "{%0,%1,%2,%3}, {%4,%5,%6,%7}, {%8,%9}, {%0,%1,%2,%3};"
        : "+f"(d[0]), "+f"(d[1]), "+f"(d[2]), "+f"(d[3])
        : "r"(a[0]), "r"(a[1]), "r"(a[2]), "r"(a[3]), "r"(b[0]), "r"(b[1]));
}
__device__ __forceinline__ uint32_t smem_to_u32(const void* smem_ptr) {
    uint32_t addr;
    asm("{ .reg .u64 tmp; cvta.to.shared.u64 tmp, %1; cvt.u32.u64 %0, tmp; }"
        : "=r"(addr) : "l"(smem_ptr));
    return addr;
}
__device__ __forceinline__ float ex2f(float x) {
    float y;
    asm("ex2.approx.f32 %0, %1;" : "=f"(y) : "f"(x));
    return y;
}
__device__ __forceinline__ uint32_t pack_bf16_pair(float x0, float x1) {
    __nv_bfloat162 t = __floats2bfloat162_rn(x0, x1);
    return *(uint32_t*)&t;
}
__device__ __forceinline__ void split_f32(float x, float& h, float& l) {
    __nv_bfloat16 hb = __float2bfloat16_rn(x);
    h = __bfloat162float(hb);
    l = x - h;
}

#define CP_ASYNC16(saddr, gptr) \
    asm volatile("cp.async.cg.shared.global [%0], [%1], 16;" \
                 :: "r"(saddr), "l"(gptr))
#define CP_COMMIT()  asm volatile("cp.async.commit_group;")
#define CP_WAIT0()   asm volatile("cp.async.wait_group 0;")
#define CP_WAIT1()   asm volatile("cp.async.wait_group 1;")

// ===========================================================================
// Split kernel: fp32 -> bf16 hi/lo
// ===========================================================================
__global__ void split_kernel(const float* __restrict__ s,
                             __nv_bfloat16* __restrict__ h,
                             __nv_bfloat16* __restrict__ l, int n4)
{
    int i = blockIdx.x * blockDim.x + threadIdx.x;
    if (i >= n4) return;
    float4 v = ((const float4*)s)[i];
    float h0,l0,h1,l1,h2,l2,h3,l3;
    split_f32(v.x, h0, l0); split_f32(v.y, h1, l1);
    split_f32(v.z, h2, l2); split_f32(v.w, h3, l3);
    ((uint2*)h)[i] = make_uint2(pack_bf16_pair(h0, h1), pack_bf16_pair(h2, h3));
    ((uint2*)l)[i] = make_uint2(pack_bf16_pair(l0, l1), pack_bf16_pair(l2, l3));
}

// ===========================================================================
// cp.async bf16x3 GEMM: C = A @ B; A,B pre-split hi/lo bf16 in global.
// CTA tile 128x256, BK=32, 512 threads (16 warps, 32x64 warp tiles, 4x4).
// 3-stage cp.async ring, one barrier per k-tile. 4 warps/SMSP for latency
// hiding on the tensor pipe.
// ===========================================================================
#define GOAH 0
#define GOAL 10240
#define GOBH 20480
#define GOBL 37376
#define GSTAGE_B 54272
#define GEMM_SMEM_BYTES (3 * GSTAGE_B)   // 162816

__global__ __launch_bounds__(512, 1)
void gemm_async(const __nv_bfloat16* __restrict__ Ah, const __nv_bfloat16* __restrict__ Al,
                const __nv_bfloat16* __restrict__ Bh, const __nv_bfloat16* __restrict__ Bl,
                float* __restrict__ Cf,
                __nv_bfloat16* __restrict__ Ch, __nv_bfloat16* __restrict__ Cl,
                int M, int N, int K, float qscale, int qcols)
{
    extern __shared__ char smem[];
    const uint32_t su = smem_to_u32(smem);

    const int tid = threadIdx.x;
    const int wid = tid >> 5;
    const int lid = tid & 31;
    const int brow = blockIdx.y * 128;
    const int bcol = blockIdx.x * 256;

    const int wr = wid >> 2;     // 0..3 -> m offset wr*32
    const int wc = wid & 3;      // 0..3 -> n offset wc*64

    const int nkt = K >> 5;

    // copy-thread assignments (512 threads)
    const int ar  = tid >> 2;            // A row 0..127
    const int ac  = tid & 3;             // A 16B chunk 0..3
    const int br  = tid >> 4;            // B row 0..31
    const int bc  = (tid & 15) * 2;      // B chunk base (2 chunks of 16B)

    auto issue_tile = [&](int kt) {
        const uint32_t sb = su + (uint32_t)(kt % 3) * GSTAGE_B;
        const int k0 = kt << 5;
        const __nv_bfloat16* gah = Ah + (size_t)(brow + ar) * K + k0 + ac * 8;
        const __nv_bfloat16* gal = Al + (size_t)(brow + ar) * K + k0 + ac * 8;
        CP_ASYNC16(sb + GOAH + ar * 80 + ac * 16, gah);
        CP_ASYNC16(sb + GOAL + ar * 80 + ac * 16, gal);
        const __nv_bfloat16* gbh = Bh + (size_t)(k0 + br) * N + bcol + bc * 8;
        const __nv_bfloat16* gbl = Bl + (size_t)(k0 + br) * N + bcol + bc * 8;
        uint32_t sbh = sb + GOBH + br * 528 + bc * 16;
        uint32_t sbl = sb + GOBL + br * 528 + bc * 16;
        CP_ASYNC16(sbh,      gbh);
        CP_ASYNC16(sbh + 16, gbh + 8);
        CP_ASYNC16(sbl,      gbl);
        CP_ASYNC16(sbl + 16, gbl + 8);
    };

    float acc[2][8][4];
#pragma unroll
    for (int i = 0; i < 2; i++)
#pragma unroll
        for (int j = 0; j < 8; j++)
#pragma unroll
            for (int q = 0; q < 4; q++) acc[i][j][q] = 0.f;

    issue_tile(0); CP_COMMIT();
    issue_tile(1); CP_COMMIT();

    for (int kt = 0; kt < nkt; kt++) {
        if (kt + 1 < nkt) { CP_WAIT1(); } else { CP_WAIT0(); }
        __syncthreads();
        if (kt + 2 < nkt) { issue_tile(kt + 2); CP_COMMIT(); }

        const uint32_t sb = su + (uint32_t)(kt % 3) * GSTAGE_B;
#pragma unroll
        for (int ks = 0; ks < 2; ks++) {
            uint32_t ah[2][4], al[2][4];
#pragma unroll
            for (int mi = 0; mi < 2; mi++) {
                uint32_t row = wr * 32 + mi * 16 + (lid & 15);
                uint32_t col = ks * 16 + (lid >> 4) * 8;
                uint32_t off = row * 80 + col * 2;
                ldsm_x4(ah[mi], sb + GOAH + off);
                ldsm_x4(al[mi], sb + GOAL + off);
            }
#pragma unroll
            for (int nb = 0; nb < 4; nb++) {
                uint32_t bh[4], bl[4];
                uint32_t row = ks * 16 + (lid & 15);
                uint32_t col = wc * 64 + nb * 16 + (lid >> 4) * 8;
                uint32_t off = row * 528 + col * 2;
                ldsm_x4_t(bh, sb + GOBH + off);
                ldsm_x4_t(bl, sb + GOBL + off);
#pragma unroll
                for (int pass = 0; pass < 3; pass++) {
#pragma unroll
                    for (int mi = 0; mi < 2; mi++) {
                        const uint32_t* af = (pass == 2) ? al[mi] : ah[mi];
                        const uint32_t* bf = (pass == 1) ? bl : bh;
                        mma16816(acc[mi][nb * 2],     af, &bf[0]);
                        mma16816(acc[mi][nb * 2 + 1], af, &bf[2]);
                    }
                }
            }
        }
    }

    // ---- epilogue ----
    const int qrow = lid >> 2;
    const int qcol = (lid & 3) * 2;
#pragma unroll
    for (int mi = 0; mi < 2; mi++) {
        int r0 = brow + wr * 32 + mi * 16 + qrow;
#pragma unroll
        for (int nb8 = 0; nb8 < 8; nb8++) {
            int c0 = bcol + wc * 64 + nb8 * 8 + qcol;
            float* d = acc[mi][nb8];
            if (Cf) {
                *(float2*)(Cf + (size_t)r0 * N + c0)       = make_float2(d[0], d[1]);
                *(float2*)(Cf + (size_t)(r0 + 8) * N + c0) = make_float2(d[2], d[3]);
            } else {
                const float sc = (c0 < qcols) ? qscale : 1.f;
                float h0,l0,h1,l1;
                split_f32(d[0] * sc, h0, l0); split_f32(d[1] * sc, h1, l1);
                *(uint32_t*)(Ch + (size_t)r0 * N + c0) = pack_bf16_pair(h0, h1);
                *(uint32_t*)(Cl + (size_t)r0 * N + c0) = pack_bf16_pair(l0, l1);
                split_f32(d[2] * sc, h0, l0); split_f32(d[3] * sc, h1, l1);
                *(uint32_t*)(Ch + (size_t)(r0 + 8) * N + c0) = pack_bf16_pair(h0, h1);
                *(uint32_t*)(Cl + (size_t)(r0 + 8) * N + c0) = pack_bf16_pair(l0, l1);
            }
        }
    }
}

// ===========================================================================
// HMMA flash attention, bf16x3, cp.async-fed K/V (pre-split in g_qkvh/l).
// Grid: (SEQ/256, NH, BATCH). 512 threads = 16 warps; warp w owns q rows
// [w*16, w*16+16). Q persists in smem; K/V 3-stage ring, 1 barrier/block.
// ===========================================================================
#define SK 72
#define AQHI 0
#define AQLO (256 * SK * 2)            // 36864
#define AKV  (2 * 256 * SK * 2)        // 73728
#define KVST (4 * 64 * SK * 2)         // 36864 per stage
#define OKHI 0
#define OKLO (64 * SK * 2)             // 9216
#define OVHI (2 * 64 * SK * 2)
#define OVLO (3 * 64 * SK * 2)
#define ATTN_SMEM_BYTES (AKV + 3 * KVST)   // 184320

__global__ __launch_bounds__(512, 1)
void attn_hmma()
{
    extern __shared__ char dsm[];
    const uint32_t su = smem_to_u32(dsm);

    const int tid = threadIdx.x;
    const int wid = tid >> 5;
    const int lid = tid & 31;
    const int b  = blockIdx.z;
    const int h  = blockIdx.y;
    const int q0 = blockIdx.x * 256;

    const uint32_t uQhi = su + AQHI, uQlo = su + AQLO;

    // KV copy assignment (512 thr): arr = tid>>7 (0:Kh 1:Kl 2:Vh 3:Vl),
    // row = (tid>>1)&63, chunk half = (tid&1)*4
    const int cv_arr = tid >> 7;
    const int cv_r   = (tid >> 1) & 63;
    const int cv_c   = (tid & 1) * 4;
    const __nv_bfloat16* cv_base = (cv_arr & 1) ? g_qkvl : g_qkvh;
    const int cv_col = DM + (cv_arr >> 1) * DM + h * HD + cv_c * 8;

    auto issue_kv = [&](int kb) {
        const uint32_t sb = su + AKV + (uint32_t)(kb % 3) * KVST
                            + cv_arr * (64 * SK * 2) + cv_r * (SK * 2) + cv_c * 16;
        const __nv_bfloat16* gp = cv_base +
            (size_t)(b * SEQ + kb * 64 + cv_r) * QKVN + cv_col;
#pragma unroll
        for (int c = 0; c < 4; c++)
            CP_ASYNC16(sb + c * 16, gp + c * 8);
    };

    // ---- issue Q + KV block 0 as group 0
    {
        const int qr = tid >> 1;
        const __nv_bfloat16* gq =
            ((tid & 1) ? g_qkvl : g_qkvh) + (size_t)(b * SEQ + q0 + qr) * QKVN + h * HD;
        uint32_t sq = ((tid & 1) ? uQlo : uQhi) + qr * (SK * 2);
#pragma unroll
        for (int c = 0; c < 8; c++)
            CP_ASYNC16(sq + c * 16, gq + c * 8);
    }
    issue_kv(0); CP_COMMIT();
    issue_kv(1); CP_COMMIT();

    float o[8][4];
#pragma unroll
    for (int j = 0; j < 8; j++)
#pragma unroll
        for (int q = 0; q < 4; q++) o[j][q] = 0.f;
    float m0 = -1e30f, m1 = -1e30f, l0 = 0.f, l1 = 0.f;

    for (int kb = 0; kb < SEQ / 64; kb++) {
        if (kb + 1 < SEQ / 64) { CP_WAIT1(); } else { CP_WAIT0(); }
        __syncthreads();
        if (kb + 2 < SEQ / 64) { issue_kv(kb + 2); CP_COMMIT(); }

        const uint32_t stB = su + AKV + (uint32_t)(kb % 3) * KVST;
        const uint32_t uKhi = stB + OKHI, uKlo = stB + OKLO;
        const uint32_t uVhi = stB + OVHI, uVlo = stB + OVLO;

        // ---- S = Q K^T  (16 x 64 per warp), bf16x3
        float s[8][4];
#pragma unroll
        for (int j = 0; j < 8; j++)
#pragma unroll
            for (int q = 0; q < 4; q++) s[j][q] = 0.f;

#pragma unroll
        for (int t = 0; t < 4; t++) {
            uint32_t qh[4], ql[4];
            {
                uint32_t row = wid * 16 + (lid & 15);
                uint32_t off = (row * SK + t * 16 + (lid >> 4) * 8) * 2;
                ldsm_x4(qh, uQhi + off);
                ldsm_x4(ql, uQlo + off);
            }
#pragma unroll
            for (int j2 = 0; j2 < 4; j2++) {
                uint32_t kh[4], kl[4];
                uint32_t off = ((j2 * 16 + (lid & 7) + ((lid >> 4) & 1) * 8) * SK
                                + t * 16 + ((lid >> 3) & 1) * 8) * 2;
                ldsm_x4(kh, uKhi + off);
                ldsm_x4(kl, uKlo + off);
                float* d0 = s[j2 * 2];
                float* d1 = s[j2 * 2 + 1];
                mma16816(d0, qh, &kh[0]); mma16816(d1, qh, &kh[2]);
                mma16816(d0, qh, &kl[0]); mma16816(d1, qh, &kl[2]);
                mma16816(d0, ql, &kh[0]); mma16816(d1, ql, &kh[2]);
            }
        }

        // ---- online softmax (log2 domain) + pack P
        uint32_t phi[4][4], plo[4][4];
        {
            float mx0 = s[0][0], mx1 = s[0][2];
#pragma unroll
            for (int j = 0; j < 8; j++) {
                mx0 = fmaxf(mx0, fmaxf(s[j][0], s[j][1]));
                mx1 = fmaxf(mx1, fmaxf(s[j][2], s[j][3]));
            }
            mx0 = fmaxf(mx0, __shfl_xor_sync(0xffffffff, mx0, 1));
            mx0 = fmaxf(mx0, __shfl_xor_sync(0xffffffff, mx0, 2));
            mx1 = fmaxf(mx1, __shfl_xor_sync(0xffffffff, mx1, 1));
            mx1 = fmaxf(mx1, __shfl_xor_sync(0xffffffff, mx1, 2));

            const float mn0 = fmaxf(m0, mx0);
            const float mn1 = fmaxf(m1, mx1);
            const float c0 = ex2f(m0 - mn0);
            const float c1 = ex2f(m1 - mn1);
            m0 = mn0; m1 = mn1;

            float rl0 = 0.f, rl1 = 0.f;
#pragma unroll
            for (int j = 0; j < 8; j++) {
                s[j][0] = ex2f(s[j][0] - mn0); rl0 += s[j][0];
                s[j][1] = ex2f(s[j][1] - mn0); rl0 += s[j][1];
                s[j][2] = ex2f(s[j][2] - mn1); rl1 += s[j][2];
                s[j][3] = ex2f(s[j][3] - mn1); rl1 += s[j][3];
            }
            rl0 += __shfl_xor_sync(0xffffffff, rl0, 1);
            rl0 += __shfl_xor_sync(0xffffffff, rl0, 2);
            rl1 += __shfl_xor_sync(0xffffffff, rl1, 1);
            rl1 += __shfl_xor_sync(0xffffffff, rl1, 2);
            l0 = l0 * c0 + rl0;
            l1 = l1 * c1 + rl1;

#pragma unroll
            for (int j = 0; j < 8; j++) {
                o[j][0] *= c0; o[j][1] *= c0;
                o[j][2] *= c1; o[j][3] *= c1;
            }

#pragma unroll
            for (int t = 0; t < 4; t++) {
                const int j = 2 * t;
                float h0,lo0,h1,lo1;
                split_f32(s[j][0], h0, lo0);   split_f32(s[j][1], h1, lo1);
                phi[t][0] = pack_bf16_pair(h0, h1);  plo[t][0] = pack_bf16_pair(lo0, lo1);
                split_f32(s[j][2], h0, lo0);   split_f32(s[j][3], h1, lo1);
                phi[t][1] = pack_bf16_pair(h0, h1);  plo[t][1] = pack_bf16_pair(lo0, lo1);
                split_f32(s[j+1][0], h0, lo0); split_f32(s[j+1][1], h1, lo1);
                phi[t][2] = pack_bf16_pair(h0, h1);  plo[t][2] = pack_bf16_pair(lo0, lo1);
                split_f32(s[j+1][2], h0, lo0); split_f32(s[j+1][3], h1, lo1);
                phi[t][3] = pack_bf16_pair(h0, h1);  plo[t][3] = pack_bf16_pair(lo0, lo1);
            }
        }

        // ---- O += P V  (bf16x3)
#pragma unroll
        for (int t = 0; t < 4; t++) {
#pragma unroll
            for (int j2 = 0; j2 < 4; j2++) {
                uint32_t vh[4], vl[4];
                uint32_t off = ((t * 16 + (lid & 15)) * SK
                                + j2 * 16 + (lid >> 4) * 8) * 2;
                ldsm_x4_t(vh, uVhi + off);
                ldsm_x4_t(vl, uVlo + off);
                float* d0 = o[j2 * 2];
                float* d1 = o[j2 * 2 + 1];
                mma16816(d0, phi[t], &vh[0]); mma16816(d1, phi[t], &vh[2]);
                mma16816(d0, phi[t], &vl[0]); mma16816(d1, phi[t], &vl[2]);
                mma16816(d0, plo[t], &vh[0]); mma16816(d1, plo[t], &vh[2]);
            }
        }
    }

    // ---- epilogue: write hi/lo bf16 attention output
    {
        const float inv0 = 1.f / l0;
        const float inv1 = 1.f / l1;
        const int gr0 = q0 + wid * 16 + (lid >> 2);
        const int col = h * HD + (lid & 3) * 2;
#pragma unroll
        for (int j = 0; j < 8; j++) {
            size_t i0 = (size_t)(b * SEQ + gr0) * DM + col + j * 8;
            size_t i1 = (size_t)(b * SEQ + gr0 + 8) * DM + col + j * 8;
            float h0,lo0,h1,lo1;
            split_f32(o[j][0] * inv0, h0, lo0);
            split_f32(o[j][1] * inv0, h1, lo1);
            *(uint32_t*)(g_atth + i0) = pack_bf16_pair(h0, h1);
            *(uint32_t*)(g_attl + i0) = pack_bf16_pair(lo0, lo1);
            split_f32(o[j][2] * inv1, h0, lo0);
            split_f32(o[j][3] * inv1, h1, lo1);
            *(uint32_t*)(g_atth + i1) = pack_bf16_pair(h0, h1);
            *(uint32_t*)(g_attl + i1) = pack_bf16_pair(lo0, lo1);
        }
    }
}

// ---------------------------------------------------------------------------
extern "C" void kernel_launch(void* const* d_in, const int* in_sizes, int n_in,
                              void* d_out, int out_size)
{
    const float* x     = (const float*)d_in[0];   // [4,2048,1024]
    const float* w_qkv = (const float*)d_in[1];   // [1024,3072]
    const float* w_out = (const float*)d_in[2];   // [1024,1024]
    float* out = (float*)d_out;                   // [4,2048,1024]

    __nv_bfloat16 *xh, *xl, *wqh, *wql, *woh, *wol, *qkvh, *qkvl, *atth, *attl;
    cudaGetSymbolAddress((void**)&xh,  g_xh);   cudaGetSymbolAddress((void**)&xl,  g_xl);
    cudaGetSymbolAddress((void**)&wqh, g_wqh);  cudaGetSymbolAddress((void**)&wql, g_wql);
    cudaGetSymbolAddress((void**)&woh, g_woh);  cudaGetSymbolAddress((void**)&wol, g_wol);
    cudaGetSymbolAddress((void**)&qkvh, g_qkvh); cudaGetSymbolAddress((void**)&qkvl, g_qkvl);
    cudaGetSymbolAddress((void**)&atth, g_atth); cudaGetSymbolAddress((void**)&attl, g_attl);

    cudaFuncSetAttribute(gemm_async,
                         cudaFuncAttributeMaxDynamicSharedMemorySize,
                         GEMM_SMEM_BYTES);
    cudaFuncSetAttribute(attn_hmma,
                         cudaFuncAttributeMaxDynamicSharedMemorySize,
                         ATTN_SMEM_BYTES);

    const float QSCALE = 0.125f * 1.4426950408889634f;   // (1/sqrt(64))*log2(e)

    // 0) split inputs to bf16 hi/lo
    {
        int n4x = MROWS * DM / 4;
        split_kernel<<<(n4x + 255) / 256, 256>>>(x, xh, xl, n4x);
        int n4q = DM * QKVN / 4;
        split_kernel<<<(n4q + 255) / 256, 256>>>(w_qkv, wqh, wql, n4q);
        int n4o = DM * DM / 4;
        split_kernel<<<(n4o + 255) / 256, 256>>>(w_out, woh, wol, n4o);
    }

    // 1) QKV projection -> hi/lo bf16 (Q columns pre-scaled by QSCALE)
    {
        dim3 grid(QKVN / 256, MROWS / 128);
        gemm_async<<<grid, 512, GEMM_SMEM_BYTES>>>(
            xh, xl, wqh, wql, nullptr, qkvh, qkvl,
            MROWS, QKVN, DM, QSCALE, DM);
    }

    // 2) Attention (HMMA flash, cp.async K/V)
    {
        dim3 grid(SEQ / 256, NH, BATCH);
        attn_hmma<<<grid, 512, ATTN_SMEM_BYTES>>>();
    }

    // 3) Output projection -> fp32 d_out
    {
        dim3 grid(DM / 256, MROWS / 128);
        gemm_async<<<grid, 512, GEMM_SMEM_BYTES>>>(
            atth, attl, woh, wol, out, nullptr, nullptr,
            MROWS, DM, DM, 1.f, 0);
    }
}